// round 7
// baseline (speedup 1.0000x reference)
#include <cuda_runtime.h>
#include <cuda_fp16.h>

// Problem constants
#define B_   2
#define T_   8
#define BT_  16
#define NQ_  128
#define NK_  128
#define DIN_ 64
#define DOUT_ 256
#define DP_  128     // d-pairs (DOUT_/2), half2-packed along d
#define DPH_ 64      // d-pairs per d-half
#define KPITCH_ 68   // words per K row (68 % 32 == 4 -> conflict-free LDS.128)

// Device-global scratch (allocation-free per harness rules)
__device__ __half2 g_Qh[B_ * NQ_ * DP_];       // 256 rows x 128 half2
__device__ __half2 g_Kh[BT_ * NK_ * DP_];      // 2048 rows x 128 half2
__device__ float   g_P[2 * BT_ * NQ_ * NK_];   // partial scores per d-half (2 MB)

__device__ __forceinline__ unsigned h2tanh_u(unsigned x) {
    unsigned r;
    asm("tanh.approx.f16x2 %0, %1;" : "=r"(r) : "r"(x));
    return r;
}
__device__ __forceinline__ unsigned hadd2_u(unsigned a, unsigned b) {
    __half2 r = __hadd2(*reinterpret_cast<__half2*>(&a),
                        *reinterpret_cast<__half2*>(&b));
    return *reinterpret_cast<unsigned*>(&r);
}

// ---------------------------------------------------------------------------
// Kernel 1: projections (fp32 math, half2 output).
// Grid = 32 Q-blocks + 256 K-blocks = 288 (8 rows each) -> 2 blocks/SM,
// 4 warps/SMSP. W loads double-buffered in registers: iteration ic+1's
// 8 float4 prefetched during ic's 64 FFMA -> latency hidden.
// Thread: cg = tid&63 (4 cols), rg = tid>>6 (2 rows).
// ---------------------------------------------------------------------------
__global__ void __launch_bounds__(256, 2) proj_kernel(
    const float* __restrict__ query, const float* __restrict__ keys,
    const float* __restrict__ Wq,    const float* __restrict__ Wk,
    const float* __restrict__ bk)
{
    __shared__ float in_sh[8][DIN_];

    const int blk = blockIdx.x;            // 0..287 (32 Q blocks, 256 K blocks)
    const bool isQ = (blk < 32);
    const int r0 = (isQ ? blk : (blk - 32)) * 8;
    const float* __restrict__ in = isQ ? query : keys;
    const float* __restrict__ W  = isQ ? Wq    : Wk;
    __half2* __restrict__ outb   = isQ ? g_Qh  : g_Kh;

    const int tid = threadIdx.x;
    const int cg = tid & 63;                // cols 4*cg..4*cg+3
    const int rg = tid >> 6;                // rows rg*2, rg*2+1

    // Stage the 8 input rows (8 x 16 float4 = 128 float4)
    if (tid < 128) {
        const int r = tid >> 4, s = tid & 15;
        *(float4*)&in_sh[r][s * 4] =
            *(const float4*)(in + (size_t)(r0 + r) * DIN_ + s * 4);
    }
    __syncthreads();

    float4 bias = make_float4(0.f, 0.f, 0.f, 0.f);
    if (!isQ) bias = *(const float4*)(bk + cg * 4);

    float4 acc0 = bias, acc1 = bias;
    const int row0 = rg * 2, row1 = rg * 2 + 1;

    // Prime the W pipeline (ic = 0)
    float4 wcur[8], wnxt[8];
#pragma unroll
    for (int i = 0; i < 8; i++)
        wcur[i] = *(const float4*)(W + (size_t)i * DOUT_ + cg * 4);

#pragma unroll
    for (int ic = 0; ic < 8; ic++) {
        if (ic < 7) {
#pragma unroll
            for (int i = 0; i < 8; i++)
                wnxt[i] = *(const float4*)(W + (size_t)((ic + 1) * 8 + i) * DOUT_ + cg * 4);
        }
#pragma unroll
        for (int i = 0; i < 8; i++) {
            const float x0 = in_sh[row0][ic * 8 + i];
            const float x1 = in_sh[row1][ic * 8 + i];
            acc0.x = fmaf(x0, wcur[i].x, acc0.x);
            acc0.y = fmaf(x0, wcur[i].y, acc0.y);
            acc0.z = fmaf(x0, wcur[i].z, acc0.z);
            acc0.w = fmaf(x0, wcur[i].w, acc0.w);
            acc1.x = fmaf(x1, wcur[i].x, acc1.x);
            acc1.y = fmaf(x1, wcur[i].y, acc1.y);
            acc1.z = fmaf(x1, wcur[i].z, acc1.z);
            acc1.w = fmaf(x1, wcur[i].w, acc1.w);
        }
#pragma unroll
        for (int i = 0; i < 8; i++) wcur[i] = wnxt[i];
    }

    {
        __half2 p0 = __floats2half2_rn(acc0.x, acc0.y);
        __half2 p1 = __floats2half2_rn(acc0.z, acc0.w);
        __half2* dst = outb + (size_t)(r0 + row0) * DP_ + cg * 2;
        dst[0] = p0; dst[1] = p1;
    }
    {
        __half2 p0 = __floats2half2_rn(acc1.x, acc1.y);
        __half2 p1 = __floats2half2_rn(acc1.z, acc1.w);
        __half2* dst = outb + (size_t)(r0 + row1) * DP_ + cg * 2;
        dst[0] = p0; dst[1] = p1;
    }
}

// ---------------------------------------------------------------------------
// Kernel 2: partial scores over a d-half (unchanged from R6).
// Grid = 512 blocks x 256 thr, 4 blocks/SM -> 32 warps/SM, 4 tanh streams
// per lane (128 chains/SM). Writes fp32 partial sums to g_P[dh].
// ---------------------------------------------------------------------------
__global__ void __launch_bounds__(256, 4) attn_partial_kernel(
    const float* __restrict__ v)
{
    __shared__ unsigned k_sh[NK_ * KPITCH_];      // 34.8 KB
    __shared__ unsigned q_sh[8][DPH_];            // 2 KB
    __shared__ unsigned v_sh[DPH_];               // 256 B

    const int blk = blockIdx.x;
    const int dh  = blk & 1;
    const int qc  = (blk >> 1) & 15;
    const int bt  = blk >> 5;
    const int b   = bt >> 3;
    const int d0  = dh * DPH_;

    const int tid  = threadIdx.x;
    const int w    = tid >> 5;
    const int lane = tid & 31;

    const __half2* __restrict__ kbase = g_Kh + (size_t)(bt * NK_) * DP_ + d0;
    const __half2* __restrict__ qbase = g_Qh + (size_t)(b * NQ_ + qc * 8) * DP_ + d0;

#pragma unroll
    for (int e = tid; e < NK_ * 16; e += 256) {
        const int nk = e >> 4, s = e & 15;
        uint4 t = *(const uint4*)(kbase + (size_t)nk * DP_ + s * 4);
        *(uint4*)&k_sh[nk * KPITCH_ + s * 4] = t;
    }
    if (tid < 128) {
        const int r = tid >> 4, s = tid & 15;
        *(uint4*)&q_sh[r][s * 4] =
            *(const uint4*)(qbase + (size_t)r * DP_ + s * 4);
    }
    if (tid >= 128 && tid < 128 + DPH_) {
        const int i = tid - 128;
        float2 vv = *(const float2*)(v + 2 * (d0 + i));
        __half2 hh = __floats2half2_rn(vv.x, vv.y);
        v_sh[i] = *reinterpret_cast<unsigned*>(&hh);
    }
    __syncthreads();

    const unsigned* __restrict__ kAp = &k_sh[(lane      ) * KPITCH_];
    const unsigned* __restrict__ kBp = &k_sh[(lane + 32 ) * KPITCH_];
    const unsigned* __restrict__ kCp = &k_sh[(lane + 64 ) * KPITCH_];
    const unsigned* __restrict__ kDp = &k_sh[(lane + 96 ) * KPITCH_];

    float accA = 0.f, accB = 0.f, accC = 0.f, accD = 0.f;

#pragma unroll 4
    for (int dp4 = 0; dp4 < DPH_; dp4 += 4) {
        unsigned kA[4], kB[4], kC[4], kD[4], qr[4], vr[4];
        *(uint4*)&kA[0] = *(const uint4*)(kAp + dp4);
        *(uint4*)&kB[0] = *(const uint4*)(kBp + dp4);
        *(uint4*)&kC[0] = *(const uint4*)(kCp + dp4);
        *(uint4*)&kD[0] = *(const uint4*)(kDp + dp4);
        *(uint4*)&qr[0] = *(const uint4*)&q_sh[w][dp4];
        *(uint4*)&vr[0] = *(const uint4*)&v_sh[dp4];

        __half2 hA = __float2half2_rn(0.f);
        __half2 hB = hA, hC = hA, hD = hA;
#pragma unroll
        for (int j = 0; j < 4; j++) {
            const unsigned tA = h2tanh_u(hadd2_u(qr[j], kA[j]));
            const unsigned tB = h2tanh_u(hadd2_u(qr[j], kB[j]));
            const unsigned tC = h2tanh_u(hadd2_u(qr[j], kC[j]));
            const unsigned tD = h2tanh_u(hadd2_u(qr[j], kD[j]));
            const __half2 vp = *reinterpret_cast<const __half2*>(&vr[j]);
            hA = __hfma2(vp, *reinterpret_cast<const __half2*>(&tA), hA);
            hB = __hfma2(vp, *reinterpret_cast<const __half2*>(&tB), hB);
            hC = __hfma2(vp, *reinterpret_cast<const __half2*>(&tC), hC);
            hD = __hfma2(vp, *reinterpret_cast<const __half2*>(&tD), hD);
        }
        float2 fA = __half22float2(hA);
        float2 fB = __half22float2(hB);
        float2 fC = __half22float2(hC);
        float2 fD = __half22float2(hD);
        accA += fA.x + fA.y;
        accB += fB.x + fB.y;
        accC += fC.x + fC.y;
        accD += fD.x + fD.y;
    }

    float* __restrict__ prow =
        g_P + ((size_t)dh * BT_ * NQ_ + (size_t)(bt * NQ_ + qc * 8 + w)) * NK_;
    prow[lane      ] = accA;
    prow[lane + 32 ] = accB;
    prow[lane + 64 ] = accC;
    prow[lane + 96 ] = accD;
}

// ---------------------------------------------------------------------------
// Kernel 3: combine d-halves + softmax (unchanged).
// ---------------------------------------------------------------------------
__global__ void __launch_bounds__(256) combine_kernel(float* __restrict__ out)
{
    const int tid  = threadIdx.x;
    const int w    = tid >> 5;
    const int lane = tid & 31;
    const int r    = blockIdx.x * 8 + w;

    const float* __restrict__ p0 = g_P + (size_t)r * NK_;
    const float* __restrict__ p1 = g_P + (size_t)(BT_ * NQ_ + r) * NK_;

    float4 a = *(const float4*)(p0 + lane * 4);
    float4 c = *(const float4*)(p1 + lane * 4);
    float4 s = make_float4(a.x + c.x, a.y + c.y, a.z + c.z, a.w + c.w);

    float m = fmaxf(fmaxf(s.x, s.y), fmaxf(s.z, s.w));
#pragma unroll
    for (int o = 16; o > 0; o >>= 1)
        m = fmaxf(m, __shfl_xor_sync(0xffffffffu, m, o));

    float4 e = make_float4(__expf(s.x - m), __expf(s.y - m),
                           __expf(s.z - m), __expf(s.w - m));
    float ssum = e.x + e.y + e.z + e.w;
#pragma unroll
    for (int o = 16; o > 0; o >>= 1)
        ssum += __shfl_xor_sync(0xffffffffu, ssum, o);

    const float rinv = 1.0f / ssum;
    float4 res = make_float4(e.x * rinv, e.y * rinv, e.z * rinv, e.w * rinv);
    *(float4*)(out + (size_t)r * NK_ + lane * 4) = res;
}

// ---------------------------------------------------------------------------
extern "C" void kernel_launch(void* const* d_in, const int* in_sizes, int n_in,
                              void* d_out, int out_size)
{
    const float* query = (const float*)d_in[0];
    const float* keys  = (const float*)d_in[1];
    const float* Wq    = (const float*)d_in[2];
    const float* Wk    = (const float*)d_in[3];
    const float* bk    = (const float*)d_in[4];
    const float* v     = (const float*)d_in[5];
    float* out = (float*)d_out;

    proj_kernel<<<288, 256>>>(query, keys, Wq, Wk, bk);
    attn_partial_kernel<<<512, 256>>>(v);
    combine_kernel<<<256, 256>>>(out);
}